// round 8
// baseline (speedup 1.0000x reference)
#include <cuda_runtime.h>

#define N_NODES 30000
#define N_EDGES 480000

typedef unsigned long long ull;

// ---------------------------------------------------------------------------
// Scratch (static device globals — no allocation)
// y layout per node: [l-block][m][ch(8)] -> l=0 @0, l=1 @8, l=2 @32. 72 f/node.
// ---------------------------------------------------------------------------
__device__ __align__(16) float g_ybuf[N_NODES * 72];

// Compacted CG (selection rule m = (p-l1)+(q-l2)+lo):
// g_cg2[combo*25 + p*5 + q] = C[m(p,q), p, q]  (0 if out of range)
__device__ float g_cg2[27 * 25];

// Fused + transposed weights (c fastest => 64-bit c-pairs are contiguous).
//   yy: base 0,    R=704 (11*64)
//   yx: base 5632, R=480 (15*32)
//   xx: base 9472, R=176 (11*16)
__device__ __align__(16) float g_wt[10880];

// ---------------------------------------------------------------------------
// f32x2 helpers
// ---------------------------------------------------------------------------
union F2U { float2 f2; ull u; float f[2]; };

__device__ __forceinline__ ull fma2(ull a, ull b, ull c) {
    ull d;
    asm("fma.rn.f32x2 %0, %1, %2, %3;" : "=l"(d) : "l"(a), "l"(b), "l"(c));
    return d;
}
__device__ __forceinline__ ull dup2(float v) {
    F2U t; t.f[0] = v; t.f[1] = v; return t.u;
}
__device__ __forceinline__ float hsum2(ull a) {
    F2U t; t.u = a; return t.f[0] + t.f[1];
}

// ---------------------------------------------------------------------------
// Kernel 1: zero y accumulator
// ---------------------------------------------------------------------------
__global__ void zero_kernel() {
    int i = blockIdx.x * blockDim.x + threadIdx.x;
    if (i < N_NODES * 18) {
        ((float4*)g_ybuf)[i] = make_float4(0.f, 0.f, 0.f, 0.f);
    }
}

// ---------------------------------------------------------------------------
// Kernel 2: Clebsch-Gordan coefficients (deterministic, tiny)
// ---------------------------------------------------------------------------
__device__ double dfac(int n) {
    double r = 1.0;
    for (int i = 2; i <= n; i++) r *= (double)i;
    return r;
}

__device__ double cg_coeff(int j1, int m1, int j2, int m2, int j, int m) {
    if (m != m1 + m2) return 0.0;
    int dj = j1 - j2; if (dj < 0) dj = -dj;
    if (j < dj || j > j1 + j2) return 0.0;
    double pre = sqrt((2.0 * j + 1.0) * dfac(j + j1 - j2) * dfac(j - j1 + j2) *
                      dfac(j1 + j2 - j) / dfac(j1 + j2 + j + 1));
    pre *= sqrt(dfac(j + m) * dfac(j - m) * dfac(j1 - m1) * dfac(j1 + m1) *
                dfac(j2 - m2) * dfac(j2 + m2));
    double s = 0.0;
    for (int k = 0; k <= j1 + j2 - j; k++) {
        int d0 = k;
        int d1 = j1 + j2 - j - k;
        int d2 = j1 - m1 - k;
        int d3 = j2 + m2 - k;
        int d4 = j - j2 + m1 + k;
        int d5 = j - j1 - m2 + k;
        if (d0 < 0 || d1 < 0 || d2 < 0 || d3 < 0 || d4 < 0 || d5 < 0) continue;
        double den = dfac(d0) * dfac(d1) * dfac(d2) * dfac(d3) * dfac(d4) * dfac(d5);
        s += ((k & 1) ? -1.0 : 1.0) / den;
    }
    return pre * s;
}

__global__ void cg_init_kernel() {
    int combo = blockIdx.x;           // 0..26
    int l1 = combo / 9;
    int l2 = (combo / 3) % 3;
    int lo = combo % 3;
    int t = threadIdx.x;              // 0..24
    int p = t / 5, q = t % 5;
    int m = (p - l1) + (q - l2) + lo; // selection rule
    float val = 0.f;
    if (p <= 2 * l1 && q <= 2 * l2 && m >= 0 && m <= 2 * lo) {
        val = (float)cg_coeff(l1, p - l1, l2, q - l2, lo, m - lo);
    }
    g_cg2[combo * 25 + t] = val;
}

// ---------------------------------------------------------------------------
// Kernel 2b: build fused+transposed weight table (unchanged from round 7)
// ---------------------------------------------------------------------------
__global__ void wt_init_kernel(const float* __restrict__ wyy0, const float* __restrict__ wyy1,
                               const float* __restrict__ wyy2, const float* __restrict__ wyx0,
                               const float* __restrict__ wyx1, const float* __restrict__ wyx2,
                               const float* __restrict__ wxx0, const float* __restrict__ wxx1,
                               const float* __restrict__ wxx2) {
    int t = blockIdx.x * blockDim.x + threadIdx.x;
    if (t >= 10880) return;

    const int  loF[11]   = {0, 0, 0, 1, 1, 1, 1, 2, 2, 2, 2};
    const int  srcK[11]  = {0, 1, 2, 0, 2, 3, 5, 0, 1, 2, 5};
    const int  pairK[11] = {-1, -1, -1, 1, -1, 4, -1, 3, -1, 4, -1};
    const float sgn[11]  = {0.f, 0.f, 0.f, 1.f, 0.f, 1.f, 0.f, 1.f, 0.f, -1.f, 0.f};

    float val;
    if (t < 5632) {                       // yy: CA=CB=8
        int u = t, R = 704, r = 64;
        int o = u / R, v = u % R;
        int pk = v / r, w = v % r, d = w / 8, c = w % 8;
        const float* S[3] = {wyy0, wyy1, wyy2};
        const float* src = S[loF[pk]];
        val = src[(srcK[pk] * r + c * 8 + d) * 8 + o];
        if (pairK[pk] >= 0)
            val += sgn[pk] * src[(pairK[pk] * r + d * 8 + c) * 8 + o];
    } else if (t < 9472) {                // yx: CA=8, CB=4, unfused 15 paths
        int u = t - 5632, R = 480, r = 32;
        int o = u / R, v = u % R;
        int pk = v / r, w = v % r, d = w / 8, c = w % 8;
        int lo = (pk < 3) ? 0 : (pk < 9 ? 1 : 2);
        int k = pk - (lo == 0 ? 0 : (lo == 1 ? 3 : 9));
        const float* S[3] = {wyx0, wyx1, wyx2};
        val = S[lo][(k * r + c * 4 + d) * 8 + o];
    } else {                              // xx: CA=CB=4, fused
        int u = t - 9472, R = 176, r = 16;
        int o = u / R, v = u % R;
        int pk = v / r, w = v % r, d = w / 4, c = w % 4;
        const float* S[3] = {wxx0, wxx1, wxx2};
        const float* src = S[loF[pk]];
        val = src[(srcK[pk] * r + c * 4 + d) * 8 + o];
        if (pairK[pk] >= 0)
            val += sgn[pk] * src[(pairK[pk] * r + d * 4 + c) * 8 + o];
    }
    g_wt[t] = val;
}

// ---------------------------------------------------------------------------
// Kernel 3: edge gather / outer-product / scatter-add (vector atomics)
// ---------------------------------------------------------------------------
__device__ __forceinline__ void red4(float* p, float a, float b, float c, float d) {
    asm volatile("red.global.add.v4.f32 [%0], {%1,%2,%3,%4};"
                 :: "l"(p), "f"(a), "f"(b), "f"(c), "f"(d) : "memory");
}

__global__ void edge_kernel(const float* __restrict__ x0,
                            const float* __restrict__ x1,
                            const float* __restrict__ x2,
                            const float* __restrict__ ev,
                            const int* __restrict__ eidx) {
    int e = blockIdx.x * blockDim.x + threadIdx.x;
    if (e >= N_EDGES) return;
    int src = eidx[e];
    int dst = eidx[N_EDGES + e];
    float2 ee = *(const float2*)(ev + 2 * e);
    float* yb = g_ybuf + (size_t)dst * 72;

    {
        float4 a = *(const float4*)(x0 + (size_t)src * 4);
        red4(yb + 0, ee.x * a.x, ee.x * a.y, ee.x * a.z, ee.x * a.w);
        red4(yb + 4, ee.y * a.x, ee.y * a.y, ee.y * a.z, ee.y * a.w);
    }
    {
        float v[12];
        const float4* p = (const float4*)(x1 + (size_t)src * 12);
        ((float4*)v)[0] = p[0];
        ((float4*)v)[1] = p[1];
        ((float4*)v)[2] = p[2];
#pragma unroll
        for (int m = 0; m < 3; m++) {
            red4(yb + 8 + m * 8,
                 ee.x * v[0 * 3 + m], ee.x * v[1 * 3 + m],
                 ee.x * v[2 * 3 + m], ee.x * v[3 * 3 + m]);
            red4(yb + 8 + m * 8 + 4,
                 ee.y * v[0 * 3 + m], ee.y * v[1 * 3 + m],
                 ee.y * v[2 * 3 + m], ee.y * v[3 * 3 + m]);
        }
    }
    {
        float v[20];
        const float4* p = (const float4*)(x2 + (size_t)src * 20);
        ((float4*)v)[0] = p[0];
        ((float4*)v)[1] = p[1];
        ((float4*)v)[2] = p[2];
        ((float4*)v)[3] = p[3];
        ((float4*)v)[4] = p[4];
#pragma unroll
        for (int m = 0; m < 5; m++) {
            red4(yb + 32 + m * 8,
                 ee.x * v[0 * 5 + m], ee.x * v[1 * 5 + m],
                 ee.x * v[2 * 5 + m], ee.x * v[3 * 5 + m]);
            red4(yb + 32 + m * 8 + 4,
                 ee.y * v[0 * 5 + m], ee.y * v[1 * 5 + m],
                 ee.y * v[2 * 5 + m], ee.y * v[3 * 5 + m]);
        }
    }
}

// ---------------------------------------------------------------------------
// Kernel 4: node compute with packed fp32x2 FMAs (c-pair packing).
// Lanes of each 64-bit value carry (c even, c odd) partial sums; horizontal
// reduction happens once at the very end.
//   A: 64-bit pairs (A[c0,p],A[c1,p]), index [p*(CA/2)+cp]
//   B: duplicated (b,b) smem, index d*Bds + q*Bqs
//   W: g_wt c-pairs (contiguous), index [d*(CA/2)+cp]
//   CG: duplicated (cg,cg) smem
// ---------------------------------------------------------------------------
template <int L1, int L2, int LO, int CA, int CB>
__device__ __forceinline__ void path2(ull* __restrict__ acc,
                                      const ull* __restrict__ A,
                                      const ull* __restrict__ Bd, int Bds, int Bqs,
                                      const ull* __restrict__ Wp,
                                      const ull* __restrict__ sCg) {
    constexpr int P = 2 * L1 + 1, Q = 2 * L2 + 1, M = 2 * LO + 1, CH = CA / 2;
    const ull* Cg = sCg + ((L1 * 3 + L2) * 3 + LO) * 25;

    ull H[CH][Q];
#pragma unroll
    for (int cp = 0; cp < CH; cp++)
#pragma unroll
        for (int q = 0; q < Q; q++) H[cp][q] = 0ull;

#pragma unroll
    for (int d = 0; d < CB; d++) {
        ull Wl[CH];
#pragma unroll
        for (int cp = 0; cp < CH; cp++) Wl[cp] = Wp[d * CH + cp];
#pragma unroll
        for (int q = 0; q < Q; q++) {
            ull b = Bd[d * Bds + q * Bqs];
#pragma unroll
            for (int cp = 0; cp < CH; cp++) H[cp][q] = fma2(Wl[cp], b, H[cp][q]);
        }
    }

#pragma unroll
    for (int p = 0; p < P; p++) {
        ull Pq[Q];
#pragma unroll
        for (int q = 0; q < Q; q++) Pq[q] = 0ull;
#pragma unroll
        for (int cp = 0; cp < CH; cp++) {
            ull a = A[p * CH + cp];
#pragma unroll
            for (int q = 0; q < Q; q++) Pq[q] = fma2(a, H[cp][q], Pq[q]);
        }
#pragma unroll
        for (int q = 0; q < Q; q++) {
            constexpr int base = LO - L1 - L2;
            int mi = p + q + base;
            if (mi >= 0 && mi < M) acc[mi] = fma2(Cg[p * 5 + q], Pq[q], acc[mi]);
        }
    }
}

#define NPB 8   // nodes per block

__global__ __launch_bounds__(128, 3)
void node_kernel(const float* __restrict__ x0, const float* __restrict__ x1,
                 const float* __restrict__ x2, float* __restrict__ out) {
    // all ull tables; odd ull strides keep 64-bit LDS conflict-free
    __shared__ ull s_yA[NPB * 37];   // y A-pairs [m*4+cp], blocks @0/4/16
    __shared__ ull s_yD[NPB * 73];   // y dup (b,b), original idx [off+q*8+d]
    __shared__ ull s_xA[NPB * 19];   // x A-pairs [m*2+cp], blocks @0/2/8
    __shared__ ull s_xD[NPB * 37];   // x dup (b,b), idx [off+d*(2l+1)+q]
    __shared__ ull s_cgD[675];       // dup CG
    __shared__ float s_acc[NPB * 8 * 9];

    int tid = threadIdx.x;
    int nblk = blockIdx.x * NPB;

    for (int i = tid; i < NPB * 36; i += 128) {      // s_yA: contiguous pairs
        int nl = i / 36, j = i % 36;
        s_yA[nl * 37 + j] = ((const ull*)g_ybuf)[(size_t)(nblk + nl) * 36 + j];
    }
    for (int i = tid; i < NPB * 72; i += 128) {      // s_yD
        int nl = i / 72, j = i % 72;
        s_yD[nl * 73 + j] = dup2(g_ybuf[(size_t)(nblk + nl) * 72 + j]);
    }
    for (int i = tid; i < NPB * 18; i += 128) {      // s_xA
        int nl = i / 18, j = i % 18;
        int gn = nblk + nl;
        float a, b;
        if (j < 2) {
            a = x0[(size_t)gn * 4 + 2 * j];
            b = x0[(size_t)gn * 4 + 2 * j + 1];
        } else if (j < 8) {
            int t2 = j - 2, m = t2 / 2, cp = t2 % 2;
            a = x1[(size_t)gn * 12 + (2 * cp) * 3 + m];
            b = x1[(size_t)gn * 12 + (2 * cp + 1) * 3 + m];
        } else {
            int t2 = j - 8, m = t2 / 2, cp = t2 % 2;
            a = x2[(size_t)gn * 20 + (2 * cp) * 5 + m];
            b = x2[(size_t)gn * 20 + (2 * cp + 1) * 5 + m];
        }
        F2U u; u.f[0] = a; u.f[1] = b;
        s_xA[nl * 19 + j] = u.u;
    }
    for (int i = tid; i < NPB * 36; i += 128) {      // s_xD
        int nl = i / 36, j = i % 36;
        int gn = nblk + nl;
        float v;
        if (j < 4)       v = x0[(size_t)gn * 4 + j];
        else if (j < 16) v = x1[(size_t)gn * 12 + (j - 4)];
        else             v = x2[(size_t)gn * 20 + (j - 16)];
        s_xD[nl * 37 + j] = dup2(v);
    }
    for (int i = tid; i < 675; i += 128) s_cgD[i] = dup2(g_cg2[i]);
    __syncthreads();

    int half = tid >> 6;
    int ht = tid & 63;
    int nl = ht & 7;
    int o = ht >> 3;
    int n = nblk + nl;

    ull acc0[1] = {0ull};
    ull acc1[3] = {0ull, 0ull, 0ull};
    ull acc2[5] = {0ull, 0ull, 0ull, 0ull, 0ull};

    if (half == 0) {
        // ---- fused y x y (11 paths), A-pairs in registers ----
        ull YA[36];
#pragma unroll
        for (int j = 0; j < 36; j++) YA[j] = s_yA[nl * 37 + j];
        const ull* yD = s_yD + nl * 73;
        const ull* wyy = (const ull*)g_wt + o * 352;

        path2<0,0,0,8,8>(acc0, YA + 0,  yD + 0,  1, 8, wyy + 0,   s_cgD);
        path2<1,1,0,8,8>(acc0, YA + 4,  yD + 8,  1, 8, wyy + 32,  s_cgD);
        path2<2,2,0,8,8>(acc0, YA + 16, yD + 32, 1, 8, wyy + 64,  s_cgD);
        path2<0,1,1,8,8>(acc1, YA + 0,  yD + 8,  1, 8, wyy + 96,  s_cgD);
        path2<1,1,1,8,8>(acc1, YA + 4,  yD + 8,  1, 8, wyy + 128, s_cgD);
        path2<1,2,1,8,8>(acc1, YA + 4,  yD + 32, 1, 8, wyy + 160, s_cgD);
        path2<2,2,1,8,8>(acc1, YA + 16, yD + 32, 1, 8, wyy + 192, s_cgD);
        path2<0,2,2,8,8>(acc2, YA + 0,  yD + 32, 1, 8, wyy + 224, s_cgD);
        path2<1,1,2,8,8>(acc2, YA + 4,  yD + 8,  1, 8, wyy + 256, s_cgD);
        path2<1,2,2,8,8>(acc2, YA + 4,  yD + 32, 1, 8, wyy + 288, s_cgD);
        path2<2,2,2,8,8>(acc2, YA + 16, yD + 32, 1, 8, wyy + 320, s_cgD);
    } else {
        // ---- y x x (15) with A = y pairs from smem; fused x x x (11) ----
        ull XA[18];
#pragma unroll
        for (int j = 0; j < 18; j++) XA[j] = s_xA[nl * 19 + j];
        const ull* yA = s_yA + nl * 37;
        const ull* xD = s_xD + nl * 37;
        const ull* wyx = (const ull*)g_wt + 2816 + o * 240;
        const ull* wxx = (const ull*)g_wt + 4736 + o * 88;

        path2<0,0,0,8,4>(acc0, yA + 0,  xD + 0,  1, 1, wyx + 0,   s_cgD);
        path2<1,1,0,8,4>(acc0, yA + 4,  xD + 4,  3, 1, wyx + 16,  s_cgD);
        path2<2,2,0,8,4>(acc0, yA + 16, xD + 16, 5, 1, wyx + 32,  s_cgD);
        path2<0,1,1,8,4>(acc1, yA + 0,  xD + 4,  3, 1, wyx + 48,  s_cgD);
        path2<1,0,1,8,4>(acc1, yA + 4,  xD + 0,  1, 1, wyx + 64,  s_cgD);
        path2<1,1,1,8,4>(acc1, yA + 4,  xD + 4,  3, 1, wyx + 80,  s_cgD);
        path2<1,2,1,8,4>(acc1, yA + 4,  xD + 16, 5, 1, wyx + 96,  s_cgD);
        path2<2,1,1,8,4>(acc1, yA + 16, xD + 4,  3, 1, wyx + 112, s_cgD);
        path2<2,2,1,8,4>(acc1, yA + 16, xD + 16, 5, 1, wyx + 128, s_cgD);
        path2<0,2,2,8,4>(acc2, yA + 0,  xD + 16, 5, 1, wyx + 144, s_cgD);
        path2<1,1,2,8,4>(acc2, yA + 4,  xD + 4,  3, 1, wyx + 160, s_cgD);
        path2<1,2,2,8,4>(acc2, yA + 4,  xD + 16, 5, 1, wyx + 176, s_cgD);
        path2<2,0,2,8,4>(acc2, yA + 16, xD + 0,  1, 1, wyx + 192, s_cgD);
        path2<2,1,2,8,4>(acc2, yA + 16, xD + 4,  3, 1, wyx + 208, s_cgD);
        path2<2,2,2,8,4>(acc2, yA + 16, xD + 16, 5, 1, wyx + 224, s_cgD);

        path2<0,0,0,4,4>(acc0, XA + 0, xD + 0,  1, 1, wxx + 0,  s_cgD);
        path2<1,1,0,4,4>(acc0, XA + 2, xD + 4,  3, 1, wxx + 8,  s_cgD);
        path2<2,2,0,4,4>(acc0, XA + 8, xD + 16, 5, 1, wxx + 16, s_cgD);
        path2<0,1,1,4,4>(acc1, XA + 0, xD + 4,  3, 1, wxx + 24, s_cgD);
        path2<1,1,1,4,4>(acc1, XA + 2, xD + 4,  3, 1, wxx + 32, s_cgD);
        path2<1,2,1,4,4>(acc1, XA + 2, xD + 16, 5, 1, wxx + 40, s_cgD);
        path2<2,2,1,4,4>(acc1, XA + 8, xD + 16, 5, 1, wxx + 48, s_cgD);
        path2<0,2,2,4,4>(acc2, XA + 0, xD + 16, 5, 1, wxx + 56, s_cgD);
        path2<1,1,2,4,4>(acc2, XA + 2, xD + 4,  3, 1, wxx + 64, s_cgD);
        path2<1,2,2,4,4>(acc2, XA + 2, xD + 16, 5, 1, wxx + 72, s_cgD);
        path2<2,2,2,4,4>(acc2, XA + 8, xD + 16, 5, 1, wxx + 80, s_cgD);
    }

    // ---- combine halves (horizontal-reduce packed lanes here) ----
    float* sa = s_acc + (o * NPB + nl) * 9;
    if (half == 1) {
        sa[0] = hsum2(acc0[0]);
        sa[1] = hsum2(acc1[0]); sa[2] = hsum2(acc1[1]); sa[3] = hsum2(acc1[2]);
        sa[4] = hsum2(acc2[0]); sa[5] = hsum2(acc2[1]); sa[6] = hsum2(acc2[2]);
        sa[7] = hsum2(acc2[3]); sa[8] = hsum2(acc2[4]);
    }
    __syncthreads();
    if (half == 0) {
        out[n * 8 + o] = hsum2(acc0[0]) + sa[0];
        float* o1 = out + 240000 + ((size_t)n * 8 + o) * 3;
        o1[0] = hsum2(acc1[0]) + sa[1];
        o1[1] = hsum2(acc1[1]) + sa[2];
        o1[2] = hsum2(acc1[2]) + sa[3];
        float* o2 = out + 960000 + ((size_t)n * 8 + o) * 5;
        o2[0] = hsum2(acc2[0]) + sa[4];
        o2[1] = hsum2(acc2[1]) + sa[5];
        o2[2] = hsum2(acc2[2]) + sa[6];
        o2[3] = hsum2(acc2[3]) + sa[7];
        o2[4] = hsum2(acc2[4]) + sa[8];
    }
}

// ---------------------------------------------------------------------------
extern "C" void kernel_launch(void* const* d_in, const int* in_sizes, int n_in,
                              void* d_out, int out_size) {
    const float* x0   = (const float*)d_in[0];
    const float* x1   = (const float*)d_in[1];
    const float* x2   = (const float*)d_in[2];
    const float* ev   = (const float*)d_in[3];
    const float* Wxx0 = (const float*)d_in[4];
    const float* Wxx1 = (const float*)d_in[5];
    const float* Wxx2 = (const float*)d_in[6];
    const float* Wyx0 = (const float*)d_in[7];
    const float* Wyx1 = (const float*)d_in[8];
    const float* Wyx2 = (const float*)d_in[9];
    const float* Wyy0 = (const float*)d_in[10];
    const float* Wyy1 = (const float*)d_in[11];
    const float* Wyy2 = (const float*)d_in[12];
    const int* eidx   = (const int*)d_in[13];
    float* out = (float*)d_out;

    zero_kernel<<<(N_NODES * 18 + 255) / 256, 256>>>();
    cg_init_kernel<<<27, 25>>>();
    wt_init_kernel<<<(10880 + 255) / 256, 256>>>(Wyy0, Wyy1, Wyy2,
                                                 Wyx0, Wyx1, Wyx2,
                                                 Wxx0, Wxx1, Wxx2);
    edge_kernel<<<(N_EDGES + 255) / 256, 256>>>(x0, x1, x2, ev, eidx);
    node_kernel<<<N_NODES / NPB, 128>>>(x0, x1, x2, out);
}

// round 9
// speedup vs baseline: 1.6590x; 1.6590x over previous
#include <cuda_runtime.h>

#define N_NODES 30000
#define N_EDGES 480000

// ---------------------------------------------------------------------------
// Scratch (static device globals — no allocation)
// y layout per node: [l-block][m][ch(8)] -> l=0 @0, l=1 @8, l=2 @32. 72 f/node.
// ---------------------------------------------------------------------------
__device__ __align__(16) float g_ybuf[N_NODES * 72];

// Compacted CG (selection rule m = (p-l1)+(q-l2)+lo):
// g_cg2[combo*25 + p*5 + q] = C[m(p,q), p, q]  (0 if out of range)
__device__ float g_cg2[27 * 25];

// Orientation-optimized fused weights, layout per path [d*CA + c] (c = A-side
// channel, fastest). Regions: yy 11 paths (o-stride 704) @0; yx 15 paths
// (o-stride 480) @5632; xx 11 paths (o-stride 176) @9472.
__device__ __align__(16) float g_wt[10880];

// ---------------------------------------------------------------------------
// Kernel 1: zero y accumulator
// ---------------------------------------------------------------------------
__global__ void zero_kernel() {
    int i = blockIdx.x * blockDim.x + threadIdx.x;
    if (i < N_NODES * 18) {
        ((float4*)g_ybuf)[i] = make_float4(0.f, 0.f, 0.f, 0.f);
    }
}

// ---------------------------------------------------------------------------
// Kernel 2: Clebsch-Gordan coefficients (deterministic, tiny)
// ---------------------------------------------------------------------------
__device__ double dfac(int n) {
    double r = 1.0;
    for (int i = 2; i <= n; i++) r *= (double)i;
    return r;
}

__device__ double cg_coeff(int j1, int m1, int j2, int m2, int j, int m) {
    if (m != m1 + m2) return 0.0;
    int dj = j1 - j2; if (dj < 0) dj = -dj;
    if (j < dj || j > j1 + j2) return 0.0;
    double pre = sqrt((2.0 * j + 1.0) * dfac(j + j1 - j2) * dfac(j - j1 + j2) *
                      dfac(j1 + j2 - j) / dfac(j1 + j2 + j + 1));
    pre *= sqrt(dfac(j + m) * dfac(j - m) * dfac(j1 - m1) * dfac(j1 + m1) *
                dfac(j2 - m2) * dfac(j2 + m2));
    double s = 0.0;
    for (int k = 0; k <= j1 + j2 - j; k++) {
        int d0 = k;
        int d1 = j1 + j2 - j - k;
        int d2 = j1 - m1 - k;
        int d3 = j2 + m2 - k;
        int d4 = j - j2 + m1 + k;
        int d5 = j - j1 - m2 + k;
        if (d0 < 0 || d1 < 0 || d2 < 0 || d3 < 0 || d4 < 0 || d5 < 0) continue;
        double den = dfac(d0) * dfac(d1) * dfac(d2) * dfac(d3) * dfac(d4) * dfac(d5);
        s += ((k & 1) ? -1.0 : 1.0) / den;
    }
    return pre * s;
}

__global__ void cg_init_kernel() {
    int combo = blockIdx.x;           // 0..26
    int l1 = combo / 9;
    int l2 = (combo / 3) % 3;
    int lo = combo % 3;
    int t = threadIdx.x;              // 0..24
    int p = t / 5, q = t % 5;
    int m = (p - l1) + (q - l2) + lo; // selection rule
    float val = 0.f;
    if (p <= 2 * l1 && q <= 2 * l2 && m >= 0 && m <= 2 * lo) {
        val = (float)cg_coeff(l1, p - l1, l2, q - l2, lo, m - lo);
    }
    g_cg2[combo * 25 + t] = val;
}

// ---------------------------------------------------------------------------
// Kernel 2b: fused + orientation-optimized weight table.
// yy/xx fused paths (pk): exec orientation (L1,L2,LO), sources ka/kb:
//   0:(0,0,0)ka0  1:(1,1,0)ka1  2:(2,2,0)ka2
//   3:(1,0,1)ka1+kb0(+1) 4:(1,1,1)ka2 5:(2,1,1)ka4+kb3(+1) 6:(2,2,1)ka5
//   7:(2,0,2)ka3+kb0(+1) 8:(1,1,2)ka1 9:(2,1,2)ka4+kb2(-1) 10:(2,2,2)ka5
//   Weff[d*CA+c] = Wsrc[ka][(c*CB+d)] + s*Wsrc[kb][(d*CB+c)]
// yx paths (pk = src order). axF=1: exec swapped (A=x, CA=4):
//   Wexec[d*4+c] = s*Wsrc[k][(d*4+c)], s=(-1)^(ly+lx-lo).
// axF=0: exec as-is (A=y, CA=8): Wexec[d*8+c] = Wsrc[k][(c*4+d)].
// ---------------------------------------------------------------------------
__global__ void wt_init_kernel(const float* __restrict__ wyy0, const float* __restrict__ wyy1,
                               const float* __restrict__ wyy2, const float* __restrict__ wyx0,
                               const float* __restrict__ wyx1, const float* __restrict__ wyx2,
                               const float* __restrict__ wxx0, const float* __restrict__ wxx1,
                               const float* __restrict__ wxx2) {
    int t = blockIdx.x * blockDim.x + threadIdx.x;
    if (t >= 10880) return;

    const int  loF[11]  = {0, 0, 0, 1, 1, 1, 1, 2, 2, 2, 2};
    const int  kaF[11]  = {0, 1, 2, 1, 2, 4, 5, 3, 1, 4, 5};
    const int  kbF[11]  = {-1, -1, -1, 0, -1, 3, -1, 0, -1, 2, -1};
    const float sgF[11] = {0.f, 0.f, 0.f, 1.f, 0.f, 1.f, 0.f, 1.f, 0.f, -1.f, 0.f};

    float val;
    if (t < 5632) {                       // yy fused, CA=CB=8
        int o = t / 704, v = t % 704;
        int pk = v / 64, w = v % 64, d = w / 8, c = w % 8;
        const float* S[3] = {wyy0, wyy1, wyy2};
        const float* src = S[loF[pk]];
        val = src[(kaF[pk] * 64 + c * 8 + d) * 8 + o];
        if (kbF[pk] >= 0)
            val += sgF[pk] * src[(kbF[pk] * 64 + d * 8 + c) * 8 + o];
    } else if (t < 9472) {                // yx, 15 paths, per-path orientation
        int u = t - 5632;
        int o = u / 480, v = u % 480;
        int pk = v / 32, w = v % 32;
        const int  loX[15]  = {0,0,0, 1,1,1,1,1,1, 2,2,2,2,2,2};
        const int  kX[15]   = {0,1,2, 0,1,2,3,4,5, 0,1,2,3,4,5};
        const int  axF[15]  = {1,1,1, 1,0,1,1,0,1, 1,1,1,0,0,1};
        const float sgX[15] = {1.f,1.f,1.f, 1.f,0.f,-1.f,1.f,0.f,-1.f,
                               1.f,1.f,-1.f,0.f,0.f,1.f};
        const float* S[3] = {wyx0, wyx1, wyx2};
        const float* src = S[loX[pk]];
        if (axF[pk]) {                    // A=x: same linear index, sign-scaled
            val = sgX[pk] * src[(kX[pk] * 32 + w) * 8 + o];
        } else {                          // A=y: transpose c,d
            int d = w / 8, c = w % 8;
            val = src[(kX[pk] * 32 + c * 4 + d) * 8 + o];
        }
    } else {                              // xx fused, CA=CB=4
        int u = t - 9472;
        int o = u / 176, v = u % 176;
        int pk = v / 16, w = v % 16, d = w / 4, c = w % 4;
        const float* S[3] = {wxx0, wxx1, wxx2};
        const float* src = S[loF[pk]];
        val = src[(kaF[pk] * 16 + c * 4 + d) * 8 + o];
        if (kbF[pk] >= 0)
            val += sgF[pk] * src[(kbF[pk] * 16 + d * 4 + c) * 8 + o];
    }
    g_wt[t] = val;
}

// ---------------------------------------------------------------------------
// Kernel 3: edge gather / outer-product / scatter-add (vector atomics)
// ---------------------------------------------------------------------------
__device__ __forceinline__ void red4(float* p, float a, float b, float c, float d) {
    asm volatile("red.global.add.v4.f32 [%0], {%1,%2,%3,%4};"
                 :: "l"(p), "f"(a), "f"(b), "f"(c), "f"(d) : "memory");
}

__global__ void edge_kernel(const float* __restrict__ x0,
                            const float* __restrict__ x1,
                            const float* __restrict__ x2,
                            const float* __restrict__ ev,
                            const int* __restrict__ eidx) {
    int e = blockIdx.x * blockDim.x + threadIdx.x;
    if (e >= N_EDGES) return;
    int src = eidx[e];
    int dst = eidx[N_EDGES + e];
    float2 ee = *(const float2*)(ev + 2 * e);
    float* yb = g_ybuf + (size_t)dst * 72;

    {
        float4 a = *(const float4*)(x0 + (size_t)src * 4);
        red4(yb + 0, ee.x * a.x, ee.x * a.y, ee.x * a.z, ee.x * a.w);
        red4(yb + 4, ee.y * a.x, ee.y * a.y, ee.y * a.z, ee.y * a.w);
    }
    {
        float v[12];
        const float4* p = (const float4*)(x1 + (size_t)src * 12);
        ((float4*)v)[0] = p[0];
        ((float4*)v)[1] = p[1];
        ((float4*)v)[2] = p[2];
#pragma unroll
        for (int m = 0; m < 3; m++) {
            red4(yb + 8 + m * 8,
                 ee.x * v[0 * 3 + m], ee.x * v[1 * 3 + m],
                 ee.x * v[2 * 3 + m], ee.x * v[3 * 3 + m]);
            red4(yb + 8 + m * 8 + 4,
                 ee.y * v[0 * 3 + m], ee.y * v[1 * 3 + m],
                 ee.y * v[2 * 3 + m], ee.y * v[3 * 3 + m]);
        }
    }
    {
        float v[20];
        const float4* p = (const float4*)(x2 + (size_t)src * 20);
        ((float4*)v)[0] = p[0];
        ((float4*)v)[1] = p[1];
        ((float4*)v)[2] = p[2];
        ((float4*)v)[3] = p[3];
        ((float4*)v)[4] = p[4];
#pragma unroll
        for (int m = 0; m < 5; m++) {
            red4(yb + 32 + m * 8,
                 ee.x * v[0 * 5 + m], ee.x * v[1 * 5 + m],
                 ee.x * v[2 * 5 + m], ee.x * v[3 * 5 + m]);
            red4(yb + 32 + m * 8 + 4,
                 ee.y * v[0 * 5 + m], ee.y * v[1 * 5 + m],
                 ee.y * v[2 * 5 + m], ee.y * v[3 * 5 + m]);
        }
    }
}

// ---------------------------------------------------------------------------
// Kernel 4 path variants. All compute, for exec path (L1,L2,LO):
//   H[c][q] = sum_d W[d*CA+c] * B[d,q]
//   Pq[q]   = sum_c A[c,p] * H[c][q]
//   acc[m(p,q)] += CG[p,q] * Pq[q]
// ---------------------------------------------------------------------------

// yy: A, B register arrays (8ch, [c*(2l+1)+i])
template <int L1, int L2, int LO>
__device__ __forceinline__ void path_rr(float* __restrict__ acc,
                                        const float (&A)[8 * (2 * L1 + 1)],
                                        const float (&B)[8 * (2 * L2 + 1)],
                                        const float* __restrict__ Wt,
                                        const float* __restrict__ sCG) {
    constexpr int P = 2 * L1 + 1, Q = 2 * L2 + 1, M = 2 * LO + 1;
    const float* Cg = sCG + ((L1 * 3 + L2) * 3 + LO) * 25;
    float H[8][Q];
#pragma unroll
    for (int c = 0; c < 8; c++)
#pragma unroll
        for (int q = 0; q < Q; q++) H[c][q] = 0.f;
#pragma unroll
    for (int d = 0; d < 8; d++) {
        float Wc[8];
        ((float4*)Wc)[0] = ((const float4*)(Wt + d * 8))[0];
        ((float4*)Wc)[1] = ((const float4*)(Wt + d * 8))[1];
#pragma unroll
        for (int c = 0; c < 8; c++)
#pragma unroll
            for (int q = 0; q < Q; q++) H[c][q] = fmaf(Wc[c], B[d * Q + q], H[c][q]);
    }
#pragma unroll
    for (int p = 0; p < P; p++) {
        float Pq[Q];
#pragma unroll
        for (int q = 0; q < Q; q++) Pq[q] = 0.f;
#pragma unroll
        for (int c = 0; c < 8; c++) {
            float a = A[c * P + p];
#pragma unroll
            for (int q = 0; q < Q; q++) Pq[q] = fmaf(a, H[c][q], Pq[q]);
        }
#pragma unroll
        for (int q = 0; q < Q; q++) {
            constexpr int base = LO - L1 - L2;
            int mi = p + q + base;
            if (mi >= 0 && mi < M) acc[mi] = fmaf(Cg[p * 5 + q], Pq[q], acc[mi]);
        }
    }
}

// A = y registers (8ch), B = x smem ([d*Q+q], 4ch)
template <int L1, int L2, int LO>
__device__ __forceinline__ void path_rs(float* __restrict__ acc,
                                        const float (&A)[8 * (2 * L1 + 1)],
                                        const float* __restrict__ sB,
                                        const float* __restrict__ Wt,
                                        const float* __restrict__ sCG) {
    constexpr int P = 2 * L1 + 1, Q = 2 * L2 + 1, M = 2 * LO + 1;
    const float* Cg = sCG + ((L1 * 3 + L2) * 3 + LO) * 25;
    float H[8][Q];
#pragma unroll
    for (int c = 0; c < 8; c++)
#pragma unroll
        for (int q = 0; q < Q; q++) H[c][q] = 0.f;
#pragma unroll
    for (int d = 0; d < 4; d++) {
        float Bq[Q];
#pragma unroll
        for (int q = 0; q < Q; q++) Bq[q] = sB[d * Q + q];
        float Wc[8];
        ((float4*)Wc)[0] = ((const float4*)(Wt + d * 8))[0];
        ((float4*)Wc)[1] = ((const float4*)(Wt + d * 8))[1];
#pragma unroll
        for (int c = 0; c < 8; c++)
#pragma unroll
            for (int q = 0; q < Q; q++) H[c][q] = fmaf(Wc[c], Bq[q], H[c][q]);
    }
#pragma unroll
    for (int p = 0; p < P; p++) {
        float Pq[Q];
#pragma unroll
        for (int q = 0; q < Q; q++) Pq[q] = 0.f;
#pragma unroll
        for (int c = 0; c < 8; c++) {
            float a = A[c * P + p];
#pragma unroll
            for (int q = 0; q < Q; q++) Pq[q] = fmaf(a, H[c][q], Pq[q]);
        }
#pragma unroll
        for (int q = 0; q < Q; q++) {
            constexpr int base = LO - L1 - L2;
            int mi = p + q + base;
            if (mi >= 0 && mi < M) acc[mi] = fmaf(Cg[p * 5 + q], Pq[q], acc[mi]);
        }
    }
}

// A = x registers (4ch), B = y smem ([q*8+d], 8ch)
template <int L1, int L2, int LO>
__device__ __forceinline__ void path_xr(float* __restrict__ acc,
                                        const float (&A)[4 * (2 * L1 + 1)],
                                        const float* __restrict__ sBy,
                                        const float* __restrict__ Wt,
                                        const float* __restrict__ sCG) {
    constexpr int P = 2 * L1 + 1, Q = 2 * L2 + 1, M = 2 * LO + 1;
    const float* Cg = sCG + ((L1 * 3 + L2) * 3 + LO) * 25;
    float H[4][Q];
#pragma unroll
    for (int c = 0; c < 4; c++)
#pragma unroll
        for (int q = 0; q < Q; q++) H[c][q] = 0.f;
#pragma unroll
    for (int d = 0; d < 8; d++) {
        float Bq[Q];
#pragma unroll
        for (int q = 0; q < Q; q++) Bq[q] = sBy[q * 8 + d];
        float Wc[4];
        ((float4*)Wc)[0] = ((const float4*)(Wt + d * 4))[0];
#pragma unroll
        for (int c = 0; c < 4; c++)
#pragma unroll
            for (int q = 0; q < Q; q++) H[c][q] = fmaf(Wc[c], Bq[q], H[c][q]);
    }
#pragma unroll
    for (int p = 0; p < P; p++) {
        float Pq[Q];
#pragma unroll
        for (int q = 0; q < Q; q++) Pq[q] = 0.f;
#pragma unroll
        for (int c = 0; c < 4; c++) {
            float a = A[c * P + p];
#pragma unroll
            for (int q = 0; q < Q; q++) Pq[q] = fmaf(a, H[c][q], Pq[q]);
        }
#pragma unroll
        for (int q = 0; q < Q; q++) {
            constexpr int base = LO - L1 - L2;
            int mi = p + q + base;
            if (mi >= 0 && mi < M) acc[mi] = fmaf(Cg[p * 5 + q], Pq[q], acc[mi]);
        }
    }
}

// A = y smem ([p*8+c], 8ch), B = x smem ([d*Q+q], 4ch)
template <int L1, int L2, int LO>
__device__ __forceinline__ void path_ys(float* __restrict__ acc,
                                        const float* __restrict__ sAy,
                                        const float* __restrict__ sBx,
                                        const float* __restrict__ Wt,
                                        const float* __restrict__ sCG) {
    constexpr int P = 2 * L1 + 1, Q = 2 * L2 + 1, M = 2 * LO + 1;
    const float* Cg = sCG + ((L1 * 3 + L2) * 3 + LO) * 25;
    float H[8][Q];
#pragma unroll
    for (int c = 0; c < 8; c++)
#pragma unroll
        for (int q = 0; q < Q; q++) H[c][q] = 0.f;
#pragma unroll
    for (int d = 0; d < 4; d++) {
        float Bq[Q];
#pragma unroll
        for (int q = 0; q < Q; q++) Bq[q] = sBx[d * Q + q];
        float Wc[8];
        ((float4*)Wc)[0] = ((const float4*)(Wt + d * 8))[0];
        ((float4*)Wc)[1] = ((const float4*)(Wt + d * 8))[1];
#pragma unroll
        for (int c = 0; c < 8; c++)
#pragma unroll
            for (int q = 0; q < Q; q++) H[c][q] = fmaf(Wc[c], Bq[q], H[c][q]);
    }
#pragma unroll
    for (int p = 0; p < P; p++) {
        float Pq[Q];
#pragma unroll
        for (int q = 0; q < Q; q++) Pq[q] = 0.f;
#pragma unroll
        for (int c = 0; c < 8; c++) {
            float a = sAy[p * 8 + c];
#pragma unroll
            for (int q = 0; q < Q; q++) Pq[q] = fmaf(a, H[c][q], Pq[q]);
        }
#pragma unroll
        for (int q = 0; q < Q; q++) {
            constexpr int base = LO - L1 - L2;
            int mi = p + q + base;
            if (mi >= 0 && mi < M) acc[mi] = fmaf(Cg[p * 5 + q], Pq[q], acc[mi]);
        }
    }
}

// A = x registers (4ch), B = x smem ([d*Q+q], 4ch)
template <int L1, int L2, int LO>
__device__ __forceinline__ void path_xx(float* __restrict__ acc,
                                        const float (&A)[4 * (2 * L1 + 1)],
                                        const float* __restrict__ sBx,
                                        const float* __restrict__ Wt,
                                        const float* __restrict__ sCG) {
    constexpr int P = 2 * L1 + 1, Q = 2 * L2 + 1, M = 2 * LO + 1;
    const float* Cg = sCG + ((L1 * 3 + L2) * 3 + LO) * 25;
    float H[4][Q];
#pragma unroll
    for (int c = 0; c < 4; c++)
#pragma unroll
        for (int q = 0; q < Q; q++) H[c][q] = 0.f;
#pragma unroll
    for (int d = 0; d < 4; d++) {
        float Bq[Q];
#pragma unroll
        for (int q = 0; q < Q; q++) Bq[q] = sBx[d * Q + q];
        float Wc[4];
        ((float4*)Wc)[0] = ((const float4*)(Wt + d * 4))[0];
#pragma unroll
        for (int c = 0; c < 4; c++)
#pragma unroll
            for (int q = 0; q < Q; q++) H[c][q] = fmaf(Wc[c], Bq[q], H[c][q]);
    }
#pragma unroll
    for (int p = 0; p < P; p++) {
        float Pq[Q];
#pragma unroll
        for (int q = 0; q < Q; q++) Pq[q] = 0.f;
#pragma unroll
        for (int c = 0; c < 4; c++) {
            float a = A[c * P + p];
#pragma unroll
            for (int q = 0; q < Q; q++) Pq[q] = fmaf(a, H[c][q], Pq[q]);
        }
#pragma unroll
        for (int q = 0; q < Q; q++) {
            constexpr int base = LO - L1 - L2;
            int mi = p + q + base;
            if (mi >= 0 && mi < M) acc[mi] = fmaf(Cg[p * 5 + q], Pq[q], acc[mi]);
        }
    }
}

#define SY_STRIDE 73
#define SX_STRIDE 37
#define NPB 8   // nodes per block

__global__ __launch_bounds__(128, 3)
void node_kernel(const float* __restrict__ x0, const float* __restrict__ x1,
                 const float* __restrict__ x2, float* __restrict__ out) {
    __shared__ float s_y[NPB * SY_STRIDE];
    __shared__ float s_x[NPB * SX_STRIDE];
    __shared__ float s_cg[27 * 25];
    __shared__ float s_acc[NPB * 8 * 9];   // [(o*NPB+nl)*9 + k]

    int tid = threadIdx.x;
    int nblk = blockIdx.x * NPB;

    // stage y: 8 nodes x 72 floats (layout per l-block: [q*8 + c])
    for (int i = tid; i < NPB * 72; i += 128) {
        int nl = i / 72, j = i % 72;
        s_y[nl * SY_STRIDE + j] = g_ybuf[(size_t)(nblk + nl) * 72 + j];
    }
    // stage x: 8 nodes x 36 floats (straight [c*(2l+1)+m]; blocks @0/4/16)
    for (int i = tid; i < NPB * 36; i += 128) {
        int nl = i / 36, j = i % 36;
        int gn = nblk + nl;
        float v;
        if (j < 4)       v = x0[(size_t)gn * 4 + j];
        else if (j < 16) v = x1[(size_t)gn * 12 + (j - 4)];
        else             v = x2[(size_t)gn * 20 + (j - 16)];
        s_x[nl * SX_STRIDE + j] = v;
    }
    for (int i = tid; i < 27 * 25; i += 128) s_cg[i] = g_cg2[i];
    __syncthreads();

    int half = tid >> 6;
    int ht = tid & 63;
    int nl = ht & 7;
    int o = ht >> 3;
    int n = nblk + nl;

    const float* sy = s_y + nl * SY_STRIDE;
    const float* sx = s_x + nl * SX_STRIDE;

    float acc0[1] = {0.f};
    float acc1[3] = {0.f, 0.f, 0.f};
    float acc2[5] = {0.f, 0.f, 0.f, 0.f, 0.f};

    if (half == 0) {
        // y into registers: Yl[c*(2l+1)+i] from sy[off + i*8 + c]
        float Y0[8], Y1[24], Y2[40];
#pragma unroll
        for (int c = 0; c < 8; c++) Y0[c] = sy[c];
#pragma unroll
        for (int c = 0; c < 8; c++)
#pragma unroll
            for (int q = 0; q < 3; q++) Y1[c * 3 + q] = sy[8 + q * 8 + c];
#pragma unroll
        for (int c = 0; c < 8; c++)
#pragma unroll
            for (int q = 0; q < 5; q++) Y2[c * 5 + q] = sy[32 + q * 8 + c];

        // ---- fused y x y, orientation-optimized (11 paths) ----
        const float* wyy = g_wt + o * 704;
        path_rr<0,0,0>(acc0, Y0, Y0, wyy + 0,   s_cg);
        path_rr<1,1,0>(acc0, Y1, Y1, wyy + 64,  s_cg);
        path_rr<2,2,0>(acc0, Y2, Y2, wyy + 128, s_cg);
        path_rr<1,0,1>(acc1, Y1, Y0, wyy + 192, s_cg);
        path_rr<1,1,1>(acc1, Y1, Y1, wyy + 256, s_cg);
        path_rr<2,1,1>(acc1, Y2, Y1, wyy + 320, s_cg);
        path_rr<2,2,1>(acc1, Y2, Y2, wyy + 384, s_cg);
        path_rr<2,0,2>(acc2, Y2, Y0, wyy + 448, s_cg);
        path_rr<1,1,2>(acc2, Y1, Y1, wyy + 512, s_cg);
        path_rr<2,1,2>(acc2, Y2, Y1, wyy + 576, s_cg);
        path_rr<2,2,2>(acc2, Y2, Y2, wyy + 640, s_cg);

        // ---- moved yx path pk12: src (2,0,2), A=y regs, B=x0 smem ----
        const float* wyx = g_wt + 5632 + o * 480;
        path_rs<2,0,2>(acc2, Y2, sx + 0, wyx + 12 * 32, s_cg);
    } else {
        // x into registers: Xl[c*(2l+1)+p] (straight copy)
        float X0[4], X1[12], X2[20];
#pragma unroll
        for (int j = 0; j < 4; j++)  X0[j] = sx[j];
#pragma unroll
        for (int j = 0; j < 12; j++) X1[j] = sx[4 + j];
#pragma unroll
        for (int j = 0; j < 20; j++) X2[j] = sx[16 + j];

        const float* wyx = g_wt + 5632 + o * 480;
        // ---- y x x, orientation-optimized (14 paths; pk12 in half 0) ----
        path_xr<0,0,0>(acc0, X0, sy + 0,  wyx + 0 * 32,  s_cg);   // src (0,0,0)
        path_xr<1,1,0>(acc0, X1, sy + 8,  wyx + 1 * 32,  s_cg);   // src (1,1,0)
        path_xr<2,2,0>(acc0, X2, sy + 32, wyx + 2 * 32,  s_cg);   // src (2,2,0)
        path_xr<1,0,1>(acc1, X1, sy + 0,  wyx + 3 * 32,  s_cg);   // src (0,1,1)
        path_ys<1,0,1>(acc1, sy + 8,  sx + 0,  wyx + 4 * 32,  s_cg); // src (1,0,1)
        path_xr<1,1,1>(acc1, X1, sy + 8,  wyx + 5 * 32,  s_cg);   // src (1,1,1)
        path_xr<2,1,1>(acc1, X2, sy + 8,  wyx + 6 * 32,  s_cg);   // src (1,2,1)
        path_ys<2,1,1>(acc1, sy + 32, sx + 4,  wyx + 7 * 32,  s_cg); // src (2,1,1)
        path_xr<2,2,1>(acc1, X2, sy + 32, wyx + 8 * 32,  s_cg);   // src (2,2,1)
        path_xr<2,0,2>(acc2, X2, sy + 0,  wyx + 9 * 32,  s_cg);   // src (0,2,2)
        path_xr<1,1,2>(acc2, X1, sy + 8,  wyx + 10 * 32, s_cg);   // src (1,1,2)
        path_xr<2,1,2>(acc2, X2, sy + 8,  wyx + 11 * 32, s_cg);   // src (1,2,2)
        path_ys<2,1,2>(acc2, sy + 32, sx + 4,  wyx + 13 * 32, s_cg); // src (2,1,2)
        path_xr<2,2,2>(acc2, X2, sy + 32, wyx + 14 * 32, s_cg);   // src (2,2,2)

        // ---- fused x x x, orientation-optimized (11 paths) ----
        const float* wxx = g_wt + 9472 + o * 176;
        path_xx<0,0,0>(acc0, X0, sx + 0,  wxx + 0,   s_cg);
        path_xx<1,1,0>(acc0, X1, sx + 4,  wxx + 16,  s_cg);
        path_xx<2,2,0>(acc0, X2, sx + 16, wxx + 32,  s_cg);
        path_xx<1,0,1>(acc1, X1, sx + 0,  wxx + 48,  s_cg);
        path_xx<1,1,1>(acc1, X1, sx + 4,  wxx + 64,  s_cg);
        path_xx<2,1,1>(acc1, X2, sx + 4,  wxx + 80,  s_cg);
        path_xx<2,2,1>(acc1, X2, sx + 16, wxx + 96,  s_cg);
        path_xx<2,0,2>(acc2, X2, sx + 0,  wxx + 112, s_cg);
        path_xx<1,1,2>(acc2, X1, sx + 4,  wxx + 128, s_cg);
        path_xx<2,1,2>(acc2, X2, sx + 4,  wxx + 144, s_cg);
        path_xx<2,2,2>(acc2, X2, sx + 16, wxx + 160, s_cg);
    }

    // ---- combine halves via smem (stride 9, conflict-free) ----
    float* sa = s_acc + (o * NPB + nl) * 9;
    if (half == 1) {
        sa[0] = acc0[0];
        sa[1] = acc1[0]; sa[2] = acc1[1]; sa[3] = acc1[2];
        sa[4] = acc2[0]; sa[5] = acc2[1]; sa[6] = acc2[2];
        sa[7] = acc2[3]; sa[8] = acc2[4];
    }
    __syncthreads();
    if (half == 0) {
        out[n * 8 + o] = acc0[0] + sa[0];
        float* o1 = out + 240000 + ((size_t)n * 8 + o) * 3;
        o1[0] = acc1[0] + sa[1]; o1[1] = acc1[1] + sa[2]; o1[2] = acc1[2] + sa[3];
        float* o2 = out + 960000 + ((size_t)n * 8 + o) * 5;
        o2[0] = acc2[0] + sa[4]; o2[1] = acc2[1] + sa[5]; o2[2] = acc2[2] + sa[6];
        o2[3] = acc2[3] + sa[7]; o2[4] = acc2[4] + sa[8];
    }
}

// ---------------------------------------------------------------------------
extern "C" void kernel_launch(void* const* d_in, const int* in_sizes, int n_in,
                              void* d_out, int out_size) {
    const float* x0   = (const float*)d_in[0];
    const float* x1   = (const float*)d_in[1];
    const float* x2   = (const float*)d_in[2];
    const float* ev   = (const float*)d_in[3];
    const float* Wxx0 = (const float*)d_in[4];
    const float* Wxx1 = (const float*)d_in[5];
    const float* Wxx2 = (const float*)d_in[6];
    const float* Wyx0 = (const float*)d_in[7];
    const float* Wyx1 = (const float*)d_in[8];
    const float* Wyx2 = (const float*)d_in[9];
    const float* Wyy0 = (const float*)d_in[10];
    const float* Wyy1 = (const float*)d_in[11];
    const float* Wyy2 = (const float*)d_in[12];
    const int* eidx   = (const int*)d_in[13];
    float* out = (float*)d_out;

    zero_kernel<<<(N_NODES * 18 + 255) / 256, 256>>>();
    cg_init_kernel<<<27, 25>>>();
    wt_init_kernel<<<(10880 + 255) / 256, 256>>>(Wyy0, Wyy1, Wyy2,
                                                 Wyx0, Wyx1, Wyx2,
                                                 Wxx0, Wxx1, Wxx2);
    edge_kernel<<<(N_EDGES + 255) / 256, 256>>>(x0, x1, x2, ev, eidx);
    node_kernel<<<N_NODES / NPB, 128>>>(x0, x1, x2, out);
}